// round 2
// baseline (speedup 1.0000x reference)
#include <cuda_runtime.h>
#include <cuda_bf16.h>

// EdgeToVertex: tril(x) * 257x257 "plus" kernel, stride (256,1), SAME
// -> out [512, 1, 256, 1].
//
// out[b,w] = colsum(w)                 colsum(w) = sum_{r=w..255} x[b,r,w]
//          + S                          S = sum_{c=0..128} x[b,128,c]
//          - 2*x[b,128,w]     (w<=128)
//          - prefix128(w-129) (w>=129)
//
// R2: load-balanced triangle read. Rows assigned to warps cyclically
// (r % 8 == wid) so every warp issues exactly 144 coalesced 128B loads per
// lane. Per-warp partial column sums in registers (8 chunks of 32 cols),
// cross-warp reduce in smem, then row-128 prefix-scan correction.

#define NN 256
#define NB 512

__global__ __launch_bounds__(256) void etv_kernel(const float* __restrict__ x,
                                                  float* __restrict__ out) {
    const int b    = blockIdx.x;
    const int w    = threadIdx.x;          // 0..255 (output column for phase 2)
    const int wid  = w >> 5;               // warp id 0..7
    const int lane = w & 31;
    const float* __restrict__ X = x + (size_t)b * (NN * NN);

    // Phase 1: balanced triangle accumulation.
    // acc[c] = partial sum of column (c*32 + lane) over this warp's rows.
    float acc[8] = {0.f, 0.f, 0.f, 0.f, 0.f, 0.f, 0.f, 0.f};

    for (int r = wid; r < NN; r += 8) {    // warp-uniform r
        const float* row = X + r * NN;
        const int cb = r >> 5;             // boundary chunk index (0..7)
        for (int c = 0; c < cb; ++c)       // full chunks, all lanes active
            acc[c] += row[c * 32 + lane];
        if (cb * 32 + lane <= r)           // boundary chunk, lane-predicated
            acc[cb] += row[cb * 32 + lane];
    }

    // Phase 2: cross-warp column reduction.
    __shared__ float part[8][NN];
    #pragma unroll
    for (int c = 0; c < 8; ++c)
        part[wid][c * 32 + lane] = acc[c];
    __syncthreads();

    float colsum = 0.f;
    #pragma unroll
    for (int j = 0; j < 8; ++j)
        colsum += part[j][w];

    // Phase 3: row-128 prefix scan (tril keeps cols 0..128 of row 128).
    __shared__ float sdata[NN];
    const float myv = (w <= 128) ? X[128 * NN + w] : 0.f;  // L2 hit (just read)
    sdata[w] = myv;
    __syncthreads();

    #pragma unroll
    for (int off = 1; off < NN; off <<= 1) {
        float t = (w >= off) ? sdata[w - off] : 0.f;
        __syncthreads();
        sdata[w] += t;
        __syncthreads();
    }

    const float S = sdata[128];
    float res;
    if (w <= 128) {
        res = colsum + S - 2.0f * myv;       // remove r=128 from colsum, c=w from rowsum
    } else {
        res = colsum + S - sdata[w - 129];   // rowsum window cols [w-128 .. 128]
    }
    out[b * NN + w] = res;
}

extern "C" void kernel_launch(void* const* d_in, const int* in_sizes, int n_in,
                              void* d_out, int out_size) {
    const float* x = (const float*)d_in[0];
    if (n_in > 1 && in_sizes[0] != NB * NN * NN) {
        for (int i = 0; i < n_in; ++i) {
            if (in_sizes[i] == NB * NN * NN) { x = (const float*)d_in[i]; break; }
        }
    }
    float* out = (float*)d_out;
    etv_kernel<<<NB, NN>>>(x, out);
}

// round 3
// speedup vs baseline: 2.1421x; 2.1421x over previous
#include <cuda_runtime.h>
#include <cuda_bf16.h>

// EdgeToVertex: tril(x) * 257x257 "plus" kernel, stride (256,1), SAME
// -> out [512, 1, 256, 1].
//
// out[b,w] = colsum(w)                 colsum(w) = sum_{r=w..255} x[b,r,w]
//          + S                          S = sum_{c=0..128} x[b,128,c]
//          - 2*x[b,128,w]     (w<=128)
//          - prefix128(w-129) (w>=129)
//
// R3: two-kernel split. Kernel 1: 512x8 CTAs, each handles 32 rows of one
// image; thread w accumulates column w over those rows via 32 fully-unrolled
// predicated loads (MLP up to 32, coalesced 128B per warp-row). Triangle
// imbalance is absorbed by the CTA scheduler instead of an intra-CTA barrier.
// Kernel 2: reduce 8 partials per column + row-128 prefix-scan correction.

#define NN 256
#define NB 512
#define RB 32              // rows per block
#define NBLK (NN / RB)     // 8

__device__ float g_scratch[NB * NBLK * NN];

__global__ __launch_bounds__(256) void etv_partial(const float* __restrict__ x) {
    const int blk = blockIdx.x;            // row block 0..7
    const int b   = blockIdx.y;            // batch
    const int w   = threadIdx.x;           // column 0..255
    const int r0  = blk * RB;

    if (w > r0 + RB - 1) return;           // entirely above diagonal: no work

    const float* __restrict__ X = x + (size_t)b * (NN * NN);

    float acc = 0.0f;
    #pragma unroll
    for (int i = 0; i < RB; ++i) {
        const int r = r0 + i;
        if (r >= w) acc += X[r * NN + w];  // predicated, 32 independent loads
    }
    g_scratch[(b * NBLK + blk) * NN + w] = acc;
}

__global__ __launch_bounds__(256) void etv_final(const float* __restrict__ x,
                                                 float* __restrict__ out) {
    const int b = blockIdx.x;
    const int w = threadIdx.x;
    const float* __restrict__ X = x + (size_t)b * (NN * NN);

    // Sum partials; blocks with blk*32+31 < w were never written -> skip.
    const int blk0 = w >> 5;
    float colsum = 0.0f;
    #pragma unroll
    for (int blk = 0; blk < NBLK; ++blk) {
        if (blk >= blk0)
            colsum += g_scratch[(b * NBLK + blk) * NN + w];
    }

    // Row-128 prefix scan (tril keeps cols 0..128 of row 128).
    __shared__ float sdata[NN];
    const float myv = (w <= 128) ? X[128 * NN + w] : 0.0f;
    sdata[w] = myv;
    __syncthreads();

    #pragma unroll
    for (int off = 1; off < NN; off <<= 1) {
        float t = (w >= off) ? sdata[w - off] : 0.0f;
        __syncthreads();
        sdata[w] += t;
        __syncthreads();
    }

    const float S = sdata[128];
    float res;
    if (w <= 128) {
        res = colsum + S - 2.0f * myv;       // remove r=128 col term + c=w row term
    } else {
        res = colsum + S - sdata[w - 129];   // row window = cols [w-128 .. 128]
    }
    out[b * NN + w] = res;
}

extern "C" void kernel_launch(void* const* d_in, const int* in_sizes, int n_in,
                              void* d_out, int out_size) {
    const float* x = (const float*)d_in[0];
    if (n_in > 1 && in_sizes[0] != NB * NN * NN) {
        for (int i = 0; i < n_in; ++i) {
            if (in_sizes[i] == NB * NN * NN) { x = (const float*)d_in[i]; break; }
        }
    }
    float* out = (float*)d_out;

    dim3 g1(NBLK, NB);
    etv_partial<<<g1, NN>>>(x);
    etv_final<<<NB, NN>>>(x, out);
}

// round 4
// speedup vs baseline: 2.2413x; 1.0463x over previous
#include <cuda_runtime.h>
#include <cuda_bf16.h>

// EdgeToVertex: tril(x) * 257x257 "plus" kernel, stride (256,1), SAME
// -> out [512, 1, 256, 1].
//
// out[b,w] = colsum(w)                 colsum(w) = sum_{r=w..255} x[b,r,w]
//          + S                          S = sum_{c=0..128} x[b,128,c]
//          - 2*x[b,128,w]     (w<=128)
//          - prefix128(w-129) (w>=129)
//
// R4: single accumulation kernel with atomics (no finalize kernel).
//  - zero kernel initializes out (harness poisons it).
//  - main kernel: grid (8, 512); CTA (blk,b) sums 32 rows of image b into
//    per-column partials (32 fully-unrolled predicated loads -> high MLP,
//    coalesced), then REDG-accumulates into out. The blk==4 CTA (owns row
//    128) additionally computes the row-128 prefix-scan correction (its row
//    re-read is an L1/L2 hit) and merges it into its single atomic.

#define NN 256
#define NB 512
#define RB 32
#define NBLK (NN / RB)   // 8

__global__ __launch_bounds__(256) void etv_zero(float* __restrict__ out) {
    out[blockIdx.x * NN + threadIdx.x] = 0.0f;
}

__global__ __launch_bounds__(256) void etv_main(const float* __restrict__ x,
                                                float* __restrict__ out) {
    const int blk = blockIdx.x;            // row block 0..7
    const int b   = blockIdx.y;            // batch
    const int w   = threadIdx.x;           // column 0..255
    const int r0  = blk * RB;
    const float* __restrict__ X = x + (size_t)b * (NN * NN);

    if (blk != 4) {
        if (w > r0 + RB - 1) return;       // entirely above diagonal
        float acc = 0.0f;
        #pragma unroll
        for (int i = 0; i < RB; ++i) {
            const int r = r0 + i;
            if (r >= w) acc += X[r * NN + w];   // independent predicated loads
        }
        atomicAdd(&out[b * NN + w], acc);
        return;
    }

    // blk == 4: rows 128..159 + row-128 correction. All 256 threads stay
    // (syncthreads below); colsum only for w <= 159.
    float acc = 0.0f;
    if (w <= r0 + RB - 1) {
        #pragma unroll
        for (int i = 0; i < RB; ++i) {
            const int r = r0 + i;
            if (r >= w) acc += X[r * NN + w];
        }
    }

    // Row-128 prefix scan (tril keeps cols 0..128). x[128,w] for w<=128 was
    // just loaded by this CTA -> cache hit.
    __shared__ float sdata[NN];
    const float myv = (w <= 128) ? X[128 * NN + w] : 0.0f;
    sdata[w] = myv;
    __syncthreads();

    #pragma unroll
    for (int off = 1; off < NN; off <<= 1) {
        float t = (w >= off) ? sdata[w - off] : 0.0f;
        __syncthreads();
        sdata[w] += t;
        __syncthreads();
    }

    const float S = sdata[128];
    const float corr = (w <= 128) ? (S - 2.0f * myv) : (S - sdata[w - 129]);
    atomicAdd(&out[b * NN + w], acc + corr);   // acc==0 for w>159
}

extern "C" void kernel_launch(void* const* d_in, const int* in_sizes, int n_in,
                              void* d_out, int out_size) {
    const float* x = (const float*)d_in[0];
    if (n_in > 1 && in_sizes[0] != NB * NN * NN) {
        for (int i = 0; i < n_in; ++i) {
            if (in_sizes[i] == NB * NN * NN) { x = (const float*)d_in[i]; break; }
        }
    }
    float* out = (float*)d_out;

    etv_zero<<<NB, NN>>>(out);
    dim3 g(NBLK, NB);
    etv_main<<<g, NN>>>(x, out);
}

// round 5
// speedup vs baseline: 2.5130x; 1.1212x over previous
#include <cuda_runtime.h>
#include <cuda_bf16.h>

// EdgeToVertex: tril(x) * 257x257 "plus" kernel, stride (256,1), SAME
// -> out [512, 1, 256, 1].
//
// out[b,w] = colsum(w)                 colsum(w) = sum_{r=w..255} x[b,r,w]
//          + S                          S = sum_{c=0..128} x[b,128,c]
//          - 2*x[b,128,w]     (w<=128)
//          - prefix128(w-129) (w>=129)
//
// R5: float4 main kernel. Grid (8,512); CTA (blk,b) covers 32 rows. Thread t
// owns column group c4 = t&63 (cols 4c4..4c4+3) over rows
// r0 + (t>>6)*8 .. +7: 8 LDG.128, vector skipped when fully above the
// diagonal, register-masked when straddling it. smem reduce across the 4 row
// groups, then 256 spread REDG per CTA. blk==4 CTA also applies the row-128
// prefix-scan correction (row re-read is a cache hit).

#define NN 256
#define NB 512
#define RB 32
#define NBLK (NN / RB)   // 8

__global__ __launch_bounds__(256) void etv_zero(float* __restrict__ out) {
    out[blockIdx.x * NN + threadIdx.x] = 0.0f;
}

__global__ __launch_bounds__(256) void etv_main(const float* __restrict__ x,
                                                float* __restrict__ out) {
    const int blk = blockIdx.x;            // row block 0..7
    const int b   = blockIdx.y;            // batch
    const int t   = threadIdx.x;
    const int c4     = t & 63;             // float4 column group (cols 4c4..4c4+3)
    const int rowOff = t >> 6;             // 0..3 -> 8 rows each
    const int r0  = blk * RB + rowOff * 8;
    const int cbase = c4 * 4;
    const float* __restrict__ X = x + (size_t)b * (NN * NN);

    float4 acc = make_float4(0.f, 0.f, 0.f, 0.f);

    #pragma unroll
    for (int i = 0; i < 8; ++i) {
        const int r = r0 + i;
        if (cbase <= r) {                  // any component below/on diagonal
            float4 v = *reinterpret_cast<const float4*>(X + r * NN + cbase);
            const int d = r - cbase;       // 0..3 means straddling
            if (d < 3) {
                if (d < 1) v.y = 0.f;
                if (d < 2) v.z = 0.f;
                v.w = 0.f;
            }
            acc.x += v.x; acc.y += v.y; acc.z += v.z; acc.w += v.w;
        }
    }

    // Reduce the 4 row groups per column group.
    __shared__ float4 part[4][64];
    part[rowOff][c4] = acc;
    __syncthreads();

    if (t < 64) {
        float4 s = part[0][t];
        #pragma unroll
        for (int j = 1; j < 4; ++j) {
            float4 p = part[j][t];
            s.x += p.x; s.y += p.y; s.z += p.z; s.w += p.w;
        }
        float* o = &out[b * NN + t * 4];
        if (s.x != 0.f || t * 4     <= blk * RB + 31) atomicAdd(o + 0, s.x);
        if (s.y != 0.f || t * 4 + 1 <= blk * RB + 31) atomicAdd(o + 1, s.y);
        if (s.z != 0.f || t * 4 + 2 <= blk * RB + 31) atomicAdd(o + 2, s.z);
        if (s.w != 0.f || t * 4 + 3 <= blk * RB + 31) atomicAdd(o + 3, s.w);
    }

    if (blk != 4) return;

    // blk == 4 owns row 128: prefix-scan correction. w = t is the column.
    __shared__ float sdata[NN];
    const int w = t;
    const float myv = (w <= 128) ? X[128 * NN + w] : 0.f;  // cache hit
    sdata[w] = myv;
    __syncthreads();

    #pragma unroll
    for (int off = 1; off < NN; off <<= 1) {
        float tv = (w >= off) ? sdata[w - off] : 0.f;
        __syncthreads();
        sdata[w] += tv;
        __syncthreads();
    }

    const float S = sdata[128];
    const float corr = (w <= 128) ? (S - 2.0f * myv) : (S - sdata[w - 129]);
    atomicAdd(&out[b * NN + w], corr);
}

extern "C" void kernel_launch(void* const* d_in, const int* in_sizes, int n_in,
                              void* d_out, int out_size) {
    const float* x = (const float*)d_in[0];
    if (n_in > 1 && in_sizes[0] != NB * NN * NN) {
        for (int i = 0; i < n_in; ++i) {
            if (in_sizes[i] == NB * NN * NN) { x = (const float*)d_in[i]; break; }
        }
    }
    float* out = (float*)d_out;

    etv_zero<<<NB, NN>>>(out);
    dim3 g(NBLK, NB);
    etv_main<<<g, NN>>>(x, out);
}

// round 6
// speedup vs baseline: 3.0078x; 1.1969x over previous
#include <cuda_runtime.h>
#include <cuda_bf16.h>

// EdgeToVertex: tril(x) * 257x257 "plus" kernel, stride (256,1), SAME
// -> out [512, 1, 256, 1].
//
// out[b,w] = colsum(w)                 colsum(w) = sum_{r=w..255} x[b,r,w]
//          + S                          S = sum_{c=0..128} x[b,128,c]
//          - 2*x[b,128,w]     (w<=128)
//          - prefix128(w-129) (w>=129)
//
// R6: RB=64. Grid (4,512); CTA (blk,b) covers 64 rows. Thread t owns float4
// column group c4 = t&63 over 16 rows (rowOff = t>>6): 16 LDG.128 fully
// unrolled (MLP 16), vector skipped when wholly above the diagonal,
// register-masked when straddling. smem reduce over 4 row groups, 256 REDG
// per CTA. blk==2 CTA (owns row 128) adds the prefix-scan correction.

#define NN 256
#define NB 512
#define RB 64
#define NBLK (NN / RB)     // 4
#define RPT 16             // rows per thread

__global__ __launch_bounds__(256) void etv_zero(float* __restrict__ out) {
    out[blockIdx.x * NN + threadIdx.x] = 0.0f;
}

__global__ __launch_bounds__(256) void etv_main(const float* __restrict__ x,
                                                float* __restrict__ out) {
    const int blk = blockIdx.x;            // row block 0..3 (64 rows each)
    const int b   = blockIdx.y;            // batch
    const int t   = threadIdx.x;
    const int c4     = t & 63;             // column group (cols 4c4..4c4+3)
    const int rowOff = t >> 6;             // 0..3 -> 16 rows each
    const int r0  = blk * RB + rowOff * RPT;
    const int cbase = c4 * 4;
    const float* __restrict__ X = x + (size_t)b * (NN * NN);
    const float* p = X + r0 * NN + cbase;

    float4 acc = make_float4(0.f, 0.f, 0.f, 0.f);

    #pragma unroll
    for (int i = 0; i < RPT; ++i) {
        const int r = r0 + i;
        if (cbase <= r) {                  // at least one component in tril
            float4 v = *reinterpret_cast<const float4*>(p + i * NN);
            const int d = r - cbase;       // 0..3 => straddles the diagonal
            if (d < 3) {
                if (d < 1) v.y = 0.f;
                if (d < 2) v.z = 0.f;
                v.w = 0.f;
            }
            acc.x += v.x; acc.y += v.y; acc.z += v.z; acc.w += v.w;
        }
    }

    // Reduce the 4 row groups per column group.
    __shared__ float4 part[4][64];
    part[rowOff][c4] = acc;
    __syncthreads();

    if (t < 64) {
        float4 s = part[0][t];
        #pragma unroll
        for (int j = 1; j < 4; ++j) {
            float4 p4 = part[j][t];
            s.x += p4.x; s.y += p4.y; s.z += p4.z; s.w += p4.w;
        }
        const int lastrow = blk * RB + RB - 1;
        float* o = &out[b * NN + t * 4];
        if (t * 4     <= lastrow) atomicAdd(o + 0, s.x);
        if (t * 4 + 1 <= lastrow) atomicAdd(o + 1, s.y);
        if (t * 4 + 2 <= lastrow) atomicAdd(o + 2, s.z);
        if (t * 4 + 3 <= lastrow) atomicAdd(o + 3, s.w);
    }

    if (blk != 2) return;

    // blk == 2 owns row 128: prefix-scan correction (row re-read = cache hit).
    __shared__ float sdata[NN];
    const int w = t;
    const float myv = (w <= 128) ? X[128 * NN + w] : 0.f;
    sdata[w] = myv;
    __syncthreads();

    #pragma unroll
    for (int off = 1; off < NN; off <<= 1) {
        float tv = (w >= off) ? sdata[w - off] : 0.f;
        __syncthreads();
        sdata[w] += tv;
        __syncthreads();
    }

    const float S = sdata[128];
    const float corr = (w <= 128) ? (S - 2.0f * myv) : (S - sdata[w - 129]);
    atomicAdd(&out[b * NN + w], corr);
}

extern "C" void kernel_launch(void* const* d_in, const int* in_sizes, int n_in,
                              void* d_out, int out_size) {
    const float* x = (const float*)d_in[0];
    if (n_in > 1 && in_sizes[0] != NB * NN * NN) {
        for (int i = 0; i < n_in; ++i) {
            if (in_sizes[i] == NB * NN * NN) { x = (const float*)d_in[i]; break; }
        }
    }
    float* out = (float*)d_out;

    etv_zero<<<NB, NN>>>(out);
    dim3 g(NBLK, NB);
    etv_main<<<g, NN>>>(x, out);
}